// round 1
// baseline (speedup 1.0000x reference)
#include <cuda_runtime.h>

// ---------------- problem constants ----------------
#define N_EMB   50000
#define B_Q     512
#define E_DIM   16
#define K_NN    20
#define NCHUNK  32
#define CHUNK   1563          // 32*1563 = 50016 >= 50000
#define TILE    256
#define QPB     128           // queries per block (threads per block in knn kernel)
#define FLT_BIG 3.402823466e+38f
#define FULLMASK 0xffffffffu
#define BUF_CAP 16

// ---------------- scratch (__device__ globals; no allocation allowed) ----------------
__device__ float g_norm[2 * N_EMB];
__device__ float g_s[2 * B_Q * NCHUNK * K_NN];
__device__ int   g_i[2 * B_Q * NCHUNK * K_NN];
__device__ float g_feats[B_Q * 8];

// ---------------- max-heap of 20 (smallest-20 tracker) in local memory ----------------
__device__ __forceinline__ void heap_replace(float* hv, int* hi, float s, int j) {
    // replace root (current max) with s, sift down. 20 nodes -> depth <= 4.
    int p = 0;
    #pragma unroll
    for (int it = 0; it < 5; it++) {
        int l = 2 * p + 1, r = 2 * p + 2;
        int c = p; float cv = s;
        if (l < K_NN && hv[l] > cv) { c = l; cv = hv[l]; }
        if (r < K_NN && hv[r] > cv) { c = r; cv = hv[r]; }
        if (c == p) break;
        hv[p] = hv[c]; hi[p] = hi[c];
        p = c;
    }
    hv[p] = s; hi[p] = j;
}

// ---------------- kernel 0: candidate squared norms ----------------
__global__ void norm_kernel(const float* __restrict__ emb0, const float* __restrict__ emb1) {
    int t = blockIdx.x * blockDim.x + threadIdx.x;
    if (t >= 2 * N_EMB) return;
    const float* emb = (t < N_EMB) ? emb0 : emb1;
    int j = (t < N_EMB) ? t : (t - N_EMB);
    const float4* e = reinterpret_cast<const float4*>(emb) + (size_t)j * 4;
    float4 v0 = e[0], v1 = e[1], v2 = e[2], v3 = e[3];
    float s = v0.x*v0.x + v0.y*v0.y + v0.z*v0.z + v0.w*v0.w
            + v1.x*v1.x + v1.y*v1.y + v1.z*v1.z + v1.w*v1.w
            + v2.x*v2.x + v2.y*v2.y + v2.z*v2.z + v2.w*v2.w
            + v3.x*v3.x + v3.y*v3.y + v3.z*v3.z + v3.w*v3.w;
    g_norm[t] = s;
}

// ---------------- kernel 1: per-(pass, query, chunk) top-20 by score s = 0.5|e|^2 - a.e ----------------
__global__ __launch_bounds__(QPB) void knn_topk_kernel(
    const float* __restrict__ emb0, const float* __restrict__ emb1,
    const int* __restrict__ idx0, const int* __restrict__ idx1)
{
    const int chunk = blockIdx.x;
    const int qg    = blockIdx.y;
    const int pass  = blockIdx.z;

    const float* emb   = pass ? emb1 : emb0;
    const int*   idxA  = pass ? idx1 : idx0;
    const float* normv = g_norm + pass * N_EMB;

    const int q    = qg * QPB + threadIdx.x;
    const int self = idxA[q];

    // query vector in registers
    float a[E_DIM];
    {
        const float4* av = reinterpret_cast<const float4*>(emb) + (size_t)self * 4;
        float4 a0 = av[0], a1 = av[1], a2 = av[2], a3 = av[3];
        a[0]=a0.x; a[1]=a0.y; a[2]=a0.z; a[3]=a0.w;
        a[4]=a1.x; a[5]=a1.y; a[6]=a1.z; a[7]=a1.w;
        a[8]=a2.x; a[9]=a2.y; a[10]=a2.z; a[11]=a2.w;
        a[12]=a3.x; a[13]=a3.y; a[14]=a3.z; a[15]=a3.w;
    }

    // top-20 heap + append buffer (local memory)
    float hv[K_NN]; int hi[K_NN];
    #pragma unroll
    for (int k = 0; k < K_NN; k++) { hv[k] = FLT_BIG; hi[k] = 0; }
    float tau = FLT_BIG;
    float bs_[BUF_CAP]; int bj_[BUF_CAP]; int bcnt = 0;

    __shared__ float4 smE[TILE * 4];
    __shared__ float  smN[TILE];

    const int c0 = chunk * CHUNK;
    const int c1 = min(c0 + CHUNK, N_EMB);

    for (int base = c0; base < c1; base += TILE) {
        const int nc  = min(TILE, c1 - base);
        const int ncp = (nc + 1) & ~1;   // pad to even
        __syncthreads();
        {
            const float4* gE = reinterpret_cast<const float4*>(emb) + (size_t)base * 4;
            for (int i = threadIdx.x; i < nc * 4; i += QPB) smE[i] = gE[i];
            for (int i = threadIdx.x; i < nc; i += QPB)     smN[i] = normv[base + i];
            if (ncp > nc) {   // pad one dummy candidate
                if (threadIdx.x < 4) smE[nc * 4 + threadIdx.x] = make_float4(0.f, 0.f, 0.f, 0.f);
                if (threadIdx.x == 0) smN[nc] = FLT_BIG;
            }
        }
        __syncthreads();

        for (int cc = 0; cc < ncp; cc += 2) {
            const int j0 = base + cc, j1 = j0 + 1;
            float4 e0 = smE[4*cc+0], e1 = smE[4*cc+1], e2 = smE[4*cc+2], e3 = smE[4*cc+3];
            float4 f0 = smE[4*cc+4], f1v = smE[4*cc+5], f2v = smE[4*cc+6], f3v = smE[4*cc+7];

            // dot(query, cand0) with 2 accumulators for ILP
            float p0 = e0.x * a[0];
            float p1 = e0.y * a[1];
            p0 = fmaf(e0.z, a[2],  p0); p1 = fmaf(e0.w, a[3],  p1);
            p0 = fmaf(e1.x, a[4],  p0); p1 = fmaf(e1.y, a[5],  p1);
            p0 = fmaf(e1.z, a[6],  p0); p1 = fmaf(e1.w, a[7],  p1);
            p0 = fmaf(e2.x, a[8],  p0); p1 = fmaf(e2.y, a[9],  p1);
            p0 = fmaf(e2.z, a[10], p0); p1 = fmaf(e2.w, a[11], p1);
            p0 = fmaf(e3.x, a[12], p0); p1 = fmaf(e3.y, a[13], p1);
            p0 = fmaf(e3.z, a[14], p0); p1 = fmaf(e3.w, a[15], p1);
            float dot0 = p0 + p1;

            float q0 = f0.x * a[0];
            float q1 = f0.y * a[1];
            q0 = fmaf(f0.z,  a[2],  q0); q1 = fmaf(f0.w,  a[3],  q1);
            q0 = fmaf(f1v.x, a[4],  q0); q1 = fmaf(f1v.y, a[5],  q1);
            q0 = fmaf(f1v.z, a[6],  q0); q1 = fmaf(f1v.w, a[7],  q1);
            q0 = fmaf(f2v.x, a[8],  q0); q1 = fmaf(f2v.y, a[9],  q1);
            q0 = fmaf(f2v.z, a[10], q0); q1 = fmaf(f2v.w, a[11], q1);
            q0 = fmaf(f3v.x, a[12], q0); q1 = fmaf(f3v.y, a[13], q1);
            q0 = fmaf(f3v.z, a[14], q0); q1 = fmaf(f3v.w, a[15], q1);
            float dot1 = q0 + q1;

            float s0 = 0.5f * smN[cc]     - dot0;
            float s1 = 0.5f * smN[cc + 1] - dot1;

            bool push0 = (s0 < tau) && (j0 != self);
            bool push1 = (s1 < tau) && (j1 != self);
            if (push0) { bs_[bcnt] = s0; bj_[bcnt] = j0; bcnt++; }
            if (push1) { bs_[bcnt] = s1; bj_[bcnt] = j1; bcnt++; }

            if (__any_sync(FULLMASK, bcnt >= BUF_CAP - 2)) {
                if (bcnt) {
                    for (int k = 0; k < bcnt; k++) {
                        float fs = bs_[k];
                        if (fs < hv[0]) heap_replace(hv, hi, fs, bj_[k]);
                    }
                    bcnt = 0;
                }
                tau = hv[0];
            }
        }
    }

    // final flush
    if (bcnt) {
        for (int k = 0; k < bcnt; k++) {
            float fs = bs_[k];
            if (fs < hv[0]) heap_replace(hv, hi, fs, bj_[k]);
        }
    }

    const size_t o = ((size_t)(pass * B_Q + q) * NCHUNK + chunk) * K_NN;
    #pragma unroll
    for (int k = 0; k < K_NN; k++) { g_s[o + k] = hv[k]; g_i[o + k] = hi[k]; }
}

// ---------------- kernel 2: merge partial top-20s, gather yctx, compute features ----------------
__global__ void merge_kernel(
    const float* __restrict__ emb0, const float* __restrict__ emb1,
    const float* __restrict__ rctx0, const float* __restrict__ rctx1,
    const int* __restrict__ idx0, const int* __restrict__ idx1,
    const float* __restrict__ mean_in, const float* __restrict__ std_in)
{
    int t = blockIdx.x * blockDim.x + threadIdx.x;
    if (t >= 2 * B_Q) return;
    const int pass = t >> 9;
    const int q    = t & (B_Q - 1);

    const float* emb  = pass ? emb1 : emb0;
    const float* rctx = pass ? rctx1 : rctx0;
    const int self = (pass ? idx1 : idx0)[q];

    // |a|^2
    float na;
    {
        const float4* av = reinterpret_cast<const float4*>(emb) + (size_t)self * 4;
        float4 a0 = av[0], a1 = av[1], a2 = av[2], a3 = av[3];
        na = a0.x*a0.x + a0.y*a0.y + a0.z*a0.z + a0.w*a0.w
           + a1.x*a1.x + a1.y*a1.y + a1.z*a1.z + a1.w*a1.w
           + a2.x*a2.x + a2.y*a2.y + a2.z*a2.z + a2.w*a2.w
           + a3.x*a3.x + a3.y*a3.y + a3.z*a3.z + a3.w*a3.w;
    }

    float hv[K_NN]; int hi[K_NN];
    #pragma unroll
    for (int k = 0; k < K_NN; k++) { hv[k] = FLT_BIG; hi[k] = 0; }

    const float* S = g_s + (size_t)t * (NCHUNK * K_NN);
    const int*   I = g_i + (size_t)t * (NCHUNK * K_NN);
    for (int k = 0; k < NCHUNK * K_NN; k++) {
        float s = S[k];
        if (s < hv[0]) heap_replace(hv, hi, s, I[k]);
    }

    // features
    float ys[K_NN];
    float f1 = 0.f, f2n = 0.f, ysum = 0.f;
    #pragma unroll
    for (int k = 0; k < K_NN; k++) {
        float d2 = fmaxf(fmaf(2.f, hv[k], na), 0.f);
        float w  = expf(-(sqrtf(d2) + 0.001f));
        float y  = rctx[(size_t)q * N_EMB + hi[k]];
        f1  += w;
        f2n += y * w;
        ysum += y;
        ys[k] = y;
    }
    float mean = ysum * (1.0f / K_NN);
    float var = 0.f;
    #pragma unroll
    for (int k = 0; k < K_NN; k++) {
        float d = ys[k] - mean;
        var = fmaf(d, d, var);
    }
    float f3 = sqrtf(var * (1.0f / (K_NN - 1)));

    g_feats[q * 8 + pass]     = f1;
    g_feats[q * 8 + 2 + pass] = f2n / f1;
    g_feats[q * 8 + 4 + pass] = f3;
    if (pass == 0) {
        g_feats[q * 8 + 6] = mean_in[q];
        g_feats[q * 8 + 7] = std_in[q];
    }
}

// ---------------- kernel 3: tiny MLP (8 -> 64 -> {mean, std}) ----------------
__global__ void mlp_kernel(
    const float* __restrict__ W1, const float* __restrict__ b1,
    const float* __restrict__ Wm, const float* __restrict__ bm,
    const float* __restrict__ Ws, const float* __restrict__ bs,
    float* __restrict__ out)
{
    __shared__ float sW1[8 * 64];
    __shared__ float sb1[64], sWm[64], sWs[64];
    int tid = threadIdx.x;
    for (int i = tid; i < 512; i += blockDim.x) sW1[i] = W1[i];
    if (tid < 64) { sb1[tid] = b1[tid]; sWm[tid] = Wm[tid]; sWs[tid] = Ws[tid]; }
    __syncthreads();

    int q = blockIdx.x * blockDim.x + tid;
    if (q >= B_Q) return;

    float f[8];
    #pragma unroll
    for (int i = 0; i < 8; i++) f[i] = g_feats[q * 8 + i];

    float m = 0.f, sd = 0.f;
    #pragma unroll 8
    for (int j = 0; j < 64; j++) {
        float acc = sb1[j];
        #pragma unroll
        for (int i = 0; i < 8; i++) acc = fmaf(f[i], sW1[i * 64 + j], acc);
        float h = fmaxf(acc, 0.f);
        m  = fmaf(h, sWm[j], m);
        sd = fmaf(h, sWs[j], sd);
    }
    out[q]        = m  + bm[0];
    out[B_Q + q]  = sd + bs[0];
}

// ---------------- launcher ----------------
extern "C" void kernel_launch(void* const* d_in, const int* in_sizes, int n_in,
                              void* d_out, int out_size)
{
    const float* emb0    = (const float*)d_in[0];
    const float* emb1    = (const float*)d_in[1];
    const float* rctx0   = (const float*)d_in[2];
    const float* rctx1   = (const float*)d_in[3];
    const int*   idx0    = (const int*)d_in[4];
    const int*   idx1    = (const int*)d_in[5];
    const float* mean_in = (const float*)d_in[6];
    const float* std_in  = (const float*)d_in[7];
    const float* W1      = (const float*)d_in[8];
    const float* b1      = (const float*)d_in[9];
    const float* Wm      = (const float*)d_in[10];
    const float* bm      = (const float*)d_in[11];
    const float* Ws      = (const float*)d_in[12];
    const float* bs      = (const float*)d_in[13];
    float* out = (float*)d_out;

    norm_kernel<<<(2 * N_EMB + 255) / 256, 256>>>(emb0, emb1);

    dim3 g1(NCHUNK, B_Q / QPB, 2);
    knn_topk_kernel<<<g1, QPB>>>(emb0, emb1, idx0, idx1);

    merge_kernel<<<(2 * B_Q + 127) / 128, 128>>>(emb0, emb1, rctx0, rctx1,
                                                 idx0, idx1, mean_in, std_in);

    mlp_kernel<<<2, 256>>>(W1, b1, Wm, bm, Ws, bs, out);
}